// round 13
// baseline (speedup 1.0000x reference)
#include <cuda_runtime.h>
#include <cuda_bf16.h>

// ---------------- problem constants ----------------
#define B_   2
#define L_   2048
#define D_   512
#define P_   32
#define M_   1024
#define H_   8
#define HD_  64
#define WIN_ 256
#define S_   (P_ + L_)     // 2080
#define R_   (B_ * S_)     // 4160
#define EPS_ 1e-5f

// ---------------- scratch (device globals, no allocation) ----------------
__device__ float g_combined[R_ * D_];
__device__ float g_k[R_ * D_];
__device__ float g_v[R_ * D_];
__device__ float g_q[R_ * D_];
__device__ float g_w[R_ * M_];          // w_write
__device__ float g_w2[R_ * M_];         // w_read
__device__ float g_state[B_ * M_ * D_];
__device__ float g_memout[R_ * D_];
__device__ float g_h[R_ * D_];
__device__ float g_qh[R_ * D_];
__device__ float g_kh[R_ * D_];
__device__ float g_vh[R_ * D_];
__device__ float g_aout[R_ * D_];
__device__ float g_ao2[R_ * D_];
__device__ float g_h2[R_ * D_];

// ---------------- bf16 m16n8k16 MMA ----------------
#define MMA_BF16(d, a0, a1, a2, a3, b0, b1) \
    asm("mma.sync.aligned.m16n8k16.row.col.f32.bf16.bf16.f32 " \
        "{%0,%1,%2,%3}, {%4,%5,%6,%7}, {%8,%9}, {%0,%1,%2,%3};" \
        : "+f"((d)[0]), "+f"((d)[1]), "+f"((d)[2]), "+f"((d)[3]) \
        : "r"(a0), "r"(a1), "r"(a2), "r"(a3), "r"(b0), "r"(b1))

// hi/lo bf16 split of a float pair; packed words have LOW half = first elem.
__device__ __forceinline__ void hilo2(float x, float y, unsigned& h, unsigned& l) {
    __nv_bfloat162 hb = __floats2bfloat162_rn(x, y);
    float2 hf = __bfloat1622float2(hb);
    __nv_bfloat162 lb = __floats2bfloat162_rn(x - hf.x, y - hf.y);
    h = reinterpret_cast<unsigned&>(hb);
    l = reinterpret_cast<unsigned&>(lb);
}

// A-tile column permutation: (c, c+8) -> adjacent words (enables LDS.64).
__device__ __forceinline__ int sgm(int c) {
    return ((c & 7) << 1) + ((c >> 3) & 1) + (c & ~15);
}

// smem layout per buffer:
//   A: two halves AH/AL, each [16 kp][136 cols] (sgm-permuted columns)
//   B: ONE interleaved region BHL [16 kp][272], word pair {bh, bl} at 2c
#define KPS  16
#define TSTR 136
#define TSTRB 272
#define MHALF (KPS * TSTR)                  // 2176 words
#define BUFW  (4 * MHALF)                   // AH | AL | BHL(2*MHALF)
#define BF_SMEM_BYTES (2 * BUFW * 4)        // 69632 B double buffered

// ---------------- bf16 2-split GEMM core: 128x128 tile, K-slab 32 --------
// C = A @ B (+bias).  ATR=0: A [M,K] row-major.  ATR=1: A stored [K,M].
// BTR=0: B stored [K,N].  BTR=1: B stored [N,K].
template<int ATR, int BTR>
__device__ __forceinline__ void bf_core(
    const float* __restrict__ A, const float* __restrict__ Bm,
    float* __restrict__ C, int M, int N, int K, const float* __restrict__ bias) {
    extern __shared__ unsigned smg[];
    const int tid = threadIdx.x, lane = tid & 31, wid = tid >> 5;
    const int wm = (wid >> 2) * 64, wn = (wid & 3) * 32;
    const int m0 = blockIdx.y * 128, n0 = blockIdx.x * 128;

    float acc[4][4][4];
#pragma unroll
    for (int i = 0; i < 4; i++)
#pragma unroll
        for (int j = 0; j < 4; j++)
#pragma unroll
            for (int c = 0; c < 4; c++) acc[i][j][c] = 0.f;

    float4 pa[4], pb[4];   // prefetch registers (gmem -> reg -> smem)

    // ---- load phase (gmem -> regs), no smem traffic ----
    auto loadA = [&](int s) {
        const int k0 = s * 32;
        if (ATR == 0) {
            const int row = tid >> 1, kh = (tid & 1) << 4;
            const bool ok = (m0 + row) < M;
            const float* p = A + (long)(m0 + row) * K + k0 + kh;
#pragma unroll
            for (int j = 0; j < 4; j++)
                pa[j] = ok ? *(const float4*)(p + j * 4)
                           : make_float4(0.f, 0.f, 0.f, 0.f);
        } else {
            const int kp = tid >> 4, cq = (tid & 15) << 3;
            const bool ok = (m0 + cq) < M;
            const float* p0 = A + (long)(k0 + 2 * kp) * M + m0 + cq;
            const float* p1 = p0 + M;
            pa[0] = ok ? *(const float4*)(p0)     : make_float4(0.f, 0.f, 0.f, 0.f);
            pa[1] = ok ? *(const float4*)(p0 + 4) : make_float4(0.f, 0.f, 0.f, 0.f);
            pa[2] = ok ? *(const float4*)(p1)     : make_float4(0.f, 0.f, 0.f, 0.f);
            pa[3] = ok ? *(const float4*)(p1 + 4) : make_float4(0.f, 0.f, 0.f, 0.f);
        }
    };
    auto loadB = [&](int s) {
        const int k0 = s * 32;
        if (BTR == 1) {
            const int row = tid >> 1, kh = (tid & 1) << 4;
            const bool ok = (n0 + row) < N;
            const float* p = Bm + (long)(n0 + row) * K + k0 + kh;
#pragma unroll
            for (int j = 0; j < 4; j++)
                pb[j] = ok ? *(const float4*)(p + j * 4)
                           : make_float4(0.f, 0.f, 0.f, 0.f);
        } else {
            const int kp = tid >> 4, cq = (tid & 15) << 3;
            const bool ok = (n0 + cq) < N;
            const float* p0 = Bm + (long)(k0 + 2 * kp) * N + n0 + cq;
            const float* p1 = p0 + N;
            pb[0] = ok ? *(const float4*)(p0)     : make_float4(0.f, 0.f, 0.f, 0.f);
            pb[1] = ok ? *(const float4*)(p0 + 4) : make_float4(0.f, 0.f, 0.f, 0.f);
            pb[2] = ok ? *(const float4*)(p1)     : make_float4(0.f, 0.f, 0.f, 0.f);
            pb[3] = ok ? *(const float4*)(p1 + 4) : make_float4(0.f, 0.f, 0.f, 0.f);
        }
    };
    // ---- store phase (regs -> smem, with hi/lo conversion) ----
    auto storeA = [&](int b) {
        unsigned* AH = smg + b * BUFW;
        unsigned* AL = AH + MHALF;
        if (ATR == 0) {
            const int row = tid >> 1, kh = (tid & 1) << 4;
            const int rw = sgm(row);
#pragma unroll
            for (int j = 0; j < 4; j++) {
                int kp = (kh >> 1) + 2 * j;
                unsigned h0, h1, l0, l1;
                hilo2(pa[j].x, pa[j].y, h0, l0);
                hilo2(pa[j].z, pa[j].w, h1, l1);
                AH[kp * TSTR + rw] = h0; AH[(kp + 1) * TSTR + rw] = h1;
                AL[kp * TSTR + rw] = l0; AL[(kp + 1) * TSTR + rw] = l1;
            }
        } else {
            const int kp = tid >> 4, cq = (tid & 15) << 3;
            unsigned h[8], l[8];
            hilo2(pa[0].x, pa[2].x, h[0], l[0]); hilo2(pa[0].y, pa[2].y, h[1], l[1]);
            hilo2(pa[0].z, pa[2].z, h[2], l[2]); hilo2(pa[0].w, pa[2].w, h[3], l[3]);
            hilo2(pa[1].x, pa[3].x, h[4], l[4]); hilo2(pa[1].y, pa[3].y, h[5], l[5]);
            hilo2(pa[1].z, pa[3].z, h[6], l[6]); hilo2(pa[1].w, pa[3].w, h[7], l[7]);
#pragma unroll
            for (int i2 = 0; i2 < 8; i2++) {
                int sl = sgm(cq + i2);
                AH[kp * TSTR + sl] = h[i2];
                AL[kp * TSTR + sl] = l[i2];
            }
        }
    };
    auto storeB = [&](int b) {
        unsigned* BHL = smg + b * BUFW + 2 * MHALF;
        if (BTR == 1) {
            const int row = tid >> 1, kh = (tid & 1) << 4;
#pragma unroll
            for (int j = 0; j < 4; j++) {
                int kp = (kh >> 1) + 2 * j;
                unsigned h0, h1, l0, l1;
                hilo2(pb[j].x, pb[j].y, h0, l0);
                hilo2(pb[j].z, pb[j].w, h1, l1);
                *(uint2*)&BHL[kp * TSTRB + 2 * row]       = make_uint2(h0, l0);
                *(uint2*)&BHL[(kp + 1) * TSTRB + 2 * row] = make_uint2(h1, l1);
            }
        } else {
            const int kp = tid >> 4, cq = (tid & 15) << 3;
            unsigned h[8], l[8];
            hilo2(pb[0].x, pb[2].x, h[0], l[0]); hilo2(pb[0].y, pb[2].y, h[1], l[1]);
            hilo2(pb[0].z, pb[2].z, h[2], l[2]); hilo2(pb[0].w, pb[2].w, h[3], l[3]);
            hilo2(pb[1].x, pb[3].x, h[4], l[4]); hilo2(pb[1].y, pb[3].y, h[5], l[5]);
            hilo2(pb[1].z, pb[3].z, h[6], l[6]); hilo2(pb[1].w, pb[3].w, h[7], l[7]);
#pragma unroll
            for (int i2 = 0; i2 < 8; i2++)
                *(uint2*)&BHL[kp * TSTRB + 2 * (cq + i2)] = make_uint2(h[i2], l[i2]);
        }
    };

    const int slabs = K >> 5;
    loadA(0); loadB(0);
    storeA(0); storeB(0);
    __syncthreads();
    int buf = 0;

    for (int s = 0; s < slabs; s++) {
        if (s + 1 < slabs) { loadA(s + 1); loadB(s + 1); }   // LDG early
        const unsigned* AH  = smg + buf * BUFW;
        const unsigned* AL  = AH + MHALF;
        const unsigned* BHL = AH + 2 * MHALF;
#pragma unroll
        for (int t = 0; t < 2; t++) {
            const int kb  = (t * 8 + (lane & 3)) * TSTR;
            const int k4  = kb + 4 * TSTR;
            const int kbB = (t * 8 + (lane & 3)) * TSTRB;
            const int k4B = kbB + 4 * TSTRB;
            const int rsel = lane >> 2;
            unsigned bh0[4], bh1[4], bl0[4], bl1[4];
#pragma unroll
            for (int j = 0; j < 4; j++) {
                int c2 = 2 * (wn + j * 8 + rsel);
                uint2 u0 = *(const uint2*)&BHL[kbB + c2];   // {bh, bl} @ kp
                uint2 u1 = *(const uint2*)&BHL[k4B + c2];   // {bh, bl} @ kp+4
                bh0[j] = u0.x; bl0[j] = u0.y;
                bh1[j] = u1.x; bl1[j] = u1.y;
            }
#pragma unroll
            for (int i = 0; i < 4; i++) {
                const int cp = wm + i * 16 + 2 * rsel;      // sgm pair slot
                uint2 Hk0 = *(const uint2*)&AH[kb + cp];
                uint2 Hk4 = *(const uint2*)&AH[k4 + cp];
                uint2 Lk0 = *(const uint2*)&AL[kb + cp];
                uint2 Lk4 = *(const uint2*)&AL[k4 + cp];
#pragma unroll
                for (int j = 0; j < 4; j++) {
                    MMA_BF16(acc[i][j], Hk0.x, Hk0.y, Hk4.x, Hk4.y, bh0[j], bh1[j]);
                    MMA_BF16(acc[i][j], Hk0.x, Hk0.y, Hk4.x, Hk4.y, bl0[j], bl1[j]);
                    MMA_BF16(acc[i][j], Lk0.x, Lk0.y, Lk4.x, Lk4.y, bh0[j], bh1[j]);
                }
            }
        }
        if (s + 1 < slabs) { storeA(buf ^ 1); storeB(buf ^ 1); }
        __syncthreads();
        buf ^= 1;
    }

    // --- epilogue ---
    const int er = lane >> 2, ec = (lane & 3) * 2;
#pragma unroll
    for (int i = 0; i < 4; i++) {
#pragma unroll
        for (int j = 0; j < 4; j++) {
            int cc = n0 + wn + j * 8 + ec;
            float b0 = 0.f, b1 = 0.f;
            if (bias) { b0 = bias[cc]; b1 = bias[cc + 1]; }
            int r0w = m0 + wm + i * 16 + er;
            if (r0w < M)
                *(float2*)(C + (long)r0w * N + cc) =
                    make_float2(acc[i][j][0] + b0, acc[i][j][1] + b1);
            int r1w = r0w + 8;
            if (r1w < M)
                *(float2*)(C + (long)r1w * N + cc) =
                    make_float2(acc[i][j][2] + b0, acc[i][j][3] + b1);
        }
    }
}

template<int ATR, int BTR>
__global__ void __launch_bounds__(256, 2)
bf_gemm(const float* __restrict__ A, const float* __restrict__ Bm,
        float* __restrict__ C, int M, int N, int K,
        long sA, long sB, long sC, const float* __restrict__ bias) {
    bf_core<ATR, BTR>(A + blockIdx.z * sA, Bm + blockIdx.z * sB,
                      C + blockIdx.z * sC, M, N, K, bias);
}

struct Ptr3 { const float* b0; const float* b1; const float* b2;
              float* c0; float* c1; float* c2; };
__global__ void __launch_bounds__(256, 2)
bf_gemm3(const float* __restrict__ A, Ptr3 p, int M, int N, int K) {
    const float* Bm = (blockIdx.z == 0) ? p.b0 : (blockIdx.z == 1) ? p.b1 : p.b2;
    float*       C  = (blockIdx.z == 0) ? p.c0 : (blockIdx.z == 1) ? p.c1 : p.c2;
    bf_core<0, 0>(A, Bm, C, M, N, K, nullptr);
}

struct PtrW { const float* a0; const float* a1; float* c0; float* c1; };
__global__ void __launch_bounds__(256, 2)
bf_gemmW(PtrW p, const float* __restrict__ mk, int M, int N, int K) {
    bf_core<0, 1>(blockIdx.z ? p.a1 : p.a0, mk,
                  blockIdx.z ? p.c1 : p.c0, M, N, K, nullptr);
}

// ---------------- concat: combined = [persistent ; x] ----------------
__global__ void concat_kernel(const float* __restrict__ x,
                              const float* __restrict__ pm,
                              float* __restrict__ c) {
    long i = (long)blockIdx.x * 256 + threadIdx.x;
    if (i >= (long)R_ * D_) return;
    int d = (int)(i % D_);
    long sd = i / D_;
    int s = (int)(sd % S_);
    int b = (int)(sd / S_);
    c[i] = (s < P_) ? pm[s * D_ + d]
                    : x[((long)b * L_ + (s - P_)) * D_ + d];
}

// ---------------- row softmax over 1024 cols ----------------
__global__ void __launch_bounds__(256) softmax1024(float* __restrict__ w) {
    __shared__ float sh[8];
    float* row = w + (long)blockIdx.x * M_;
    const int tid = threadIdx.x;
    float4 v = *(float4*)(row + tid * 4);
    float mx = fmaxf(fmaxf(v.x, v.y), fmaxf(v.z, v.w));
#pragma unroll
    for (int o = 16; o; o >>= 1) mx = fmaxf(mx, __shfl_xor_sync(~0u, mx, o));
    if ((tid & 31) == 0) sh[tid >> 5] = mx;
    __syncthreads();
    mx = sh[0];
#pragma unroll
    for (int i = 1; i < 8; i++) mx = fmaxf(mx, sh[i]);
    v.x = __expf(v.x - mx); v.y = __expf(v.y - mx);
    v.z = __expf(v.z - mx); v.w = __expf(v.w - mx);
    float s = v.x + v.y + v.z + v.w;
#pragma unroll
    for (int o = 16; o; o >>= 1) s += __shfl_xor_sync(~0u, s, o);
    __syncthreads();
    if ((tid & 31) == 0) sh[tid >> 5] = s;
    __syncthreads();
    s = sh[0] + sh[1] + sh[2] + sh[3] + sh[4] + sh[5] + sh[6] + sh[7];
    float inv = 1.f / s;
    v.x *= inv; v.y *= inv; v.z *= inv; v.w *= inv;
    *(float4*)(row + tid * 4) = v;
}

// ---------------- layernorm, row width 512, 128 threads ----------------
__global__ void __launch_bounds__(128)
layernorm512(const float* __restrict__ in, float* __restrict__ out,
             const float* __restrict__ gw, const float* __restrict__ bw) {
    __shared__ float sh[4];
    const int tid = threadIdx.x;
    const float* row = in + (long)blockIdx.x * D_;
    float4 v = *(const float4*)(row + tid * 4);
    float s = v.x + v.y + v.z + v.w;
#pragma unroll
    for (int o = 16; o; o >>= 1) s += __shfl_xor_sync(~0u, s, o);
    if ((tid & 31) == 0) sh[tid >> 5] = s;
    __syncthreads();
    float mu = (sh[0] + sh[1] + sh[2] + sh[3]) * (1.f / 512.f);
    float dx = v.x - mu, dy = v.y - mu, dz = v.z - mu, dw = v.w - mu;
    float sq = dx * dx + dy * dy + dz * dz + dw * dw;
#pragma unroll
    for (int o = 16; o; o >>= 1) sq += __shfl_xor_sync(~0u, sq, o);
    __syncthreads();
    if ((tid & 31) == 0) sh[tid >> 5] = sq;
    __syncthreads();
    float var = (sh[0] + sh[1] + sh[2] + sh[3]) * (1.f / 512.f);
    float inv = rsqrtf(var + EPS_);
    float4 g4 = *(const float4*)(gw + tid * 4);
    float4 b4 = *(const float4*)(bw + tid * 4);
    float4 o;
    o.x = dx * inv * g4.x + b4.x;
    o.y = dy * inv * g4.y + b4.y;
    o.z = dz * inv * g4.z + b4.z;
    o.w = dw * inv * g4.w + b4.w;
    *(float4*)(out + (long)blockIdx.x * D_ + tid * 4) = o;
}

// ---------------- banded flash attention (R6 core, conflict-free smem) ----
#define QS_STR 68
#define PS_STR 69
#define ATTN_SMEM_FLOATS (64 * QS_STR + 64 * PS_STR + 64 * 64 * 2)
__global__ void __launch_bounds__(256)
attn_kernel(const float* __restrict__ qh, const float* __restrict__ kh,
            const float* __restrict__ vh, float* __restrict__ out) {
    extern __shared__ float smema[];
    float* Qs = smema;
    float* Ps = smema + 64 * QS_STR;
    float* Ks = Ps + 64 * PS_STR;
    float* Vs = Ks + 64 * 64;

    const int qt = blockIdx.x, h = blockIdx.y, b = blockIdx.z;
    const int q0 = qt * 64;
    const int tid = threadIdx.x;
    const int r = tid >> 2, cg = tid & 3;
    const int rowb = cg * 16;
    const long base = (long)b * S_ * D_ + h * HD_;

    for (int i = tid; i < 64 * 16; i += 256) {
        int rr = i >> 4, c4 = (i & 15) * 4;
        float4 qv = make_float4(0.f, 0.f, 0.f, 0.f);
        if (q0 + rr < S_)
            qv = *(const float4*)(qh + base + (long)(q0 + rr) * D_ + c4);
        *(float4*)&Qs[rr * QS_STR + c4] = qv;
    }

    float m = -1e30f, l = 0.f;
    float o[16];
#pragma unroll
    for (int i = 0; i < 16; i++) o[i] = 0.f;

    int klo = q0 - (WIN_ - 1); if (klo < 0) klo = 0;
    int khi = q0 + 63 + WIN_ - 1; if (khi > S_ - 1) khi = S_ - 1;

    for (int kt = klo >> 6; kt <= khi >> 6; ++kt) {
        const int k0 = kt << 6;
        __syncthreads();
        for (int i = tid; i < 64 * 16; i += 256) {
            int rr = i >> 4, c4 = (i & 15) * 4;
            float4 kv = make_float4(0.f, 0.f, 0.f, 0.f), vv = kv;
            if (k0 + rr < S_) {
                long g = base + (long)(k0 + rr) * D_ + c4;
                kv = *(const float4*)(kh + g);
                vv = *(const float4*)(vh + g);
            }
            *(float4*)&Ks[rr * 64 + (c4 ^ ((rr >> 4) * 8))] = kv;
            *(float4*)&Vs[rr * 64 + (c4 ^ ((c4 >> 5) * 8))] = vv;
        }
        __syncthreads();

        float sreg[16];
#pragma unroll
        for (int j = 0; j < 16; j++) sreg[j] = 0.f;
        const int kx = cg * 8;
#pragma unroll 4
        for (int d0 = 0; d0 < 64; d0 += 4) {
            float4 q4 = *(const float4*)&Qs[r * QS_STR + d0];
            const int kc = d0 ^ kx;
#pragma unroll
            for (int j = 0; j < 16; j++) {
                float4 k4 = *(const float4*)&Ks[(rowb + j) * 64 + kc];
                sreg[j] += q4.x * k4.x + q4.y * k4.y + q4.z * k4.z + q4.w * k4.w;
            }
        }

        const int qi = q0 + r;
        float tmax = -1e30f;
#pragma unroll
        for (int j = 0; j < 16; j++) {
            int kj = k0 + rowb + j;
            int diff = qi - kj; if (diff < 0) diff = -diff;
            bool valid = (kj < S_) && (diff < WIN_);
            sreg[j] = valid ? sreg[j] * 0.125f : -1e30f;
            tmax = fmaxf(tmax, sreg[j]);
        }
        tmax = fmaxf(tmax, __shfl_xor_sync(0xffffffffu, tmax, 1));
        tmax = fmaxf(tmax, __shfl_xor_sync(0xffffffffu, tmax, 2));
        float mnew = fmaxf(m, tmax);
        float alpha = __expf(m - mnew);
        float lsum = 0.f;
#pragma unroll
        for (int j = 0; j < 16; j++) {
            float p = (sreg[j] > -0.9e30f) ? __expf(sreg[j] - mnew) : 0.f;
            Ps[r * PS_STR + rowb + j] = p;
            lsum += p;
        }
        lsum += __shfl_xor_sync(0xffffffffu, lsum, 1);
        lsum += __shfl_xor_sync(0xffffffffu, lsum, 2);
        l = l * alpha + lsum;
        m = mnew;
#pragma unroll
        for (int i = 0; i < 16; i++) o[i] *= alpha;
        __syncthreads();

        const int vx = (cg >> 1) * 8;
#pragma unroll 4
        for (int j = 0; j < 64; j++) {
            float p = Ps[r * PS_STR + j];
#pragma unroll
            for (int i4 = 0; i4 < 4; i4++) {
                float4 v4 = *(const float4*)&Vs[j * 64 + ((rowb + i4 * 4) ^ vx)];
                o[i4 * 4 + 0] += p * v4.x;
                o[i4 * 4 + 1] += p * v4.y;
                o[i4 * 4 + 2] += p * v4.z;
                o[i4 * 4 + 3] += p * v4.w;
            }
        }
    }

    const int qi = q0 + r;
    if (qi < S_) {
        float inv = 1.f / l;
        float* orow = out + base + (long)qi * D_ + rowb;
#pragma unroll
        for (int i = 0; i < 16; i++) orow[i] = o[i] * inv;
    }
}

// ---------------- launch ----------------
extern "C" void kernel_launch(void* const* d_in, const int* in_sizes, int n_in,
                              void* d_out, int out_size) {
    const float* x        = (const float*)d_in[0];
    const float* pm       = (const float*)d_in[1];
    const float* mem_keys = (const float*)d_in[2];
    const float* mem_Wk   = (const float*)d_in[3];
    const float* mem_Wv   = (const float*)d_in[4];
    const float* mem_Wq   = (const float*)d_in[5];
    const float* attn_Wq  = (const float*)d_in[6];
    const float* attn_Wk  = (const float*)d_in[7];
    const float* attn_Wv  = (const float*)d_in[8];
    const float* attn_Wo  = (const float*)d_in[9];
    const float* ln1_g    = (const float*)d_in[10];
    const float* ln1_b    = (const float*)d_in[11];
    const float* ln2_g    = (const float*)d_in[12];
    const float* ln2_b    = (const float*)d_in[13];
    const float* out_W    = (const float*)d_in[14];
    const float* out_b    = (const float*)d_in[15];
    float* out = (float*)d_out;

    float *combined, *k, *v, *q, *w, *w2, *state, *memout, *h;
    float *qh, *kh, *vh, *aout, *ao2, *h2;
    cudaGetSymbolAddress((void**)&combined, g_combined);
    cudaGetSymbolAddress((void**)&k, g_k);
    cudaGetSymbolAddress((void**)&v, g_v);
    cudaGetSymbolAddress((void**)&q, g_q);
    cudaGetSymbolAddress((void**)&w, g_w);
    cudaGetSymbolAddress((void**)&w2, g_w2);
    cudaGetSymbolAddress((void**)&state, g_state);
    cudaGetSymbolAddress((void**)&memout, g_memout);
    cudaGetSymbolAddress((void**)&h, g_h);
    cudaGetSymbolAddress((void**)&qh, g_qh);
    cudaGetSymbolAddress((void**)&kh, g_kh);
    cudaGetSymbolAddress((void**)&vh, g_vh);
    cudaGetSymbolAddress((void**)&aout, g_aout);
    cudaGetSymbolAddress((void**)&ao2, g_ao2);
    cudaGetSymbolAddress((void**)&h2, g_h2);

    cudaFuncSetAttribute(attn_kernel,
                         cudaFuncAttributeMaxDynamicSharedMemorySize,
                         ATTN_SMEM_FLOATS * (int)sizeof(float));
    cudaFuncSetAttribute(bf_gemm3,
                         cudaFuncAttributeMaxDynamicSharedMemorySize, BF_SMEM_BYTES);
    cudaFuncSetAttribute(bf_gemmW,
                         cudaFuncAttributeMaxDynamicSharedMemorySize, BF_SMEM_BYTES);
    cudaFuncSetAttribute(bf_gemm<1, 0>,
                         cudaFuncAttributeMaxDynamicSharedMemorySize, BF_SMEM_BYTES);
    cudaFuncSetAttribute(bf_gemm<0, 0>,
                         cudaFuncAttributeMaxDynamicSharedMemorySize, BF_SMEM_BYTES);

    // 1. combined = [pm ; x]
    concat_kernel<<<(int)(((long)R_ * D_ + 255) / 256), 256>>>(x, pm, combined);

    const int MT = (R_ + 127) / 128;   // 33

    // 2. memory k/v/q projections
    {
        Ptr3 p{mem_Wk, mem_Wv, mem_Wq, k, v, q};
        bf_gemm3<<<dim3(4, MT, 3), 256, BF_SMEM_BYTES>>>(combined, p, R_, D_, D_);
    }

    // 3. gating: w_write = k@mkT, w_read = q@mkT  (mem_keys stored [N,K])
    {
        PtrW p{k, q, w, w2};
        bf_gemmW<<<dim3(8, MT, 2), 256, BF_SMEM_BYTES>>>(p, mem_keys, R_, M_, D_);
    }
    softmax1024<<<R_, 256>>>(w);
    softmax1024<<<R_, 256>>>(w2);

    // 4. state[b] = w_write[b]^T @ v[b]   (A stored [K=S, M=1024])
    bf_gemm<1, 0><<<dim3(4, 8, B_), 256, BF_SMEM_BYTES>>>(
        w, v, state, M_, D_, S_,
        (long)S_ * M_, (long)S_ * D_, (long)M_ * D_, nullptr);

    // 5. mem_out[b] = w_read[b] @ state[b]
    bf_gemm<0, 0><<<dim3(4, (S_ + 127) / 128, B_), 256, BF_SMEM_BYTES>>>(
        w2, state, memout, S_, D_, M_,
        (long)S_ * M_, (long)M_ * D_, (long)S_ * D_, nullptr);

    // 6. LN1
    layernorm512<<<R_, 128>>>(memout, h, ln1_g, ln1_b);

    // 7. attention projections
    {
        Ptr3 p{attn_Wq, attn_Wk, attn_Wv, qh, kh, vh};
        bf_gemm3<<<dim3(4, MT, 3), 256, BF_SMEM_BYTES>>>(h, p, R_, D_, D_);
    }

    // 8. banded flash attention
    attn_kernel<<<dim3((S_ + 63) / 64, H_, B_), 256,
                  ATTN_SMEM_FLOATS * (int)sizeof(float)>>>(qh, kh, vh, aout);

    // 9. output projection + LN2 + final linear (+bias)
    bf_gemm<0, 0><<<dim3(4, MT, 1), 256, BF_SMEM_BYTES>>>(
        aout, attn_Wo, ao2, R_, D_, D_, 0, 0, 0, nullptr);
    layernorm512<<<R_, 128>>>(ao2, h2, ln2_g, ln2_b);
    bf_gemm<0, 0><<<dim3(4, MT, 1), 256, BF_SMEM_BYTES>>>(
        h2, out_W, out, R_, D_, D_, 0, 0, 0, out_b);
}